// round 11
// baseline (speedup 1.0000x reference)
#include <cuda_runtime.h>
#include <stdint.h>

#define BATCH   8
#define NPRIOR  33600
#define TOPK    5000
#define KEEPK   750
#define CONF_TH 0.3f
#define NMS_TH  0.3f
#define NB      4096
#define CANDS   6144
#define BINSCALE (4094.0f / 0.7f)
#define KEYTH   0xBE99999Au     // key_from_float(0.3f)

#define NCOL    20
#define COLCAP  160
#define LARGECAP 256
#define INVCOLW (1.0f / 64.0f)
#define SPAD    5120            // TOPK padded to chunk multiple (128)

typedef unsigned long long ull;

// ---------------- device scratch ----------------
__device__ int    g_hist[BATCH * NB];        // zero at load; every pass restores zero
__device__ int    g_bincur[BATCH * NB];
__device__ int    g_suf[BATCH * (NB + 2)];
__device__ int    g_cb[BATCH];
__device__ int    g_ctot[BATCH];
__device__ ull    g_cand[(size_t)BATCH * CANDS];

// ---------------- helpers ----------------
__device__ __forceinline__ unsigned key_from_float(float f) {
    unsigned u = __float_as_uint(f);
    return (u & 0x80000000u) ? ~u : (u | 0x80000000u);
}
__device__ __forceinline__ float float_from_key(unsigned u) {
    return __uint_as_float((u & 0x80000000u) ? (u ^ 0x80000000u) : ~u);
}
__device__ __forceinline__ int bin_of(float m) {
    if (!(m > CONF_TH)) return 0;
    int b = (int)((m - CONF_TH) * BINSCALE);
    if (b > 4094) b = 4094;
    return 1 + b;
}
__device__ __forceinline__ int colclamp(float x) {
    int c = (int)floorf(x * INVCOLW);
    return c < 0 ? 0 : (c > NCOL - 1 ? NCOL - 1 : c);
}
// box = (x1,x2,y1,y2); w,h>0 so reference clamps are identity; division exact
__device__ __forceinline__ bool pair_sup(float4 a, float4 b, float ab) {
    float xo = fminf(a.y, b.y) - fmaxf(a.x, b.x);
    float yo = fminf(a.w, b.w) - fmaxf(a.z, b.z);
    if (xo > 0.0f && yo > 0.0f) {
        float inter = xo * yo;
        float aa = (a.y - a.x) * (a.w - a.z);
        return inter / (aa + ab - inter + 1e-12f) > NMS_TH;
    }
    return false;
}
__device__ __forceinline__ void prior_of(unsigned idx, float& px, float& py, float& ps) {
    if (idx < 25600u)      { ps = 8.0f;  px = (float)((idx % 160u) * 8u); py = (float)((idx / 160u) * 8u); }
    else if (idx < 32000u) { unsigned j = idx - 25600u; ps = 16.0f; px = (float)((j % 80u) * 16u); py = (float)((j / 80u) * 16u); }
    else                   { unsigned j = idx - 32000u; ps = 32.0f; px = (float)((j % 40u) * 32u); py = (float)((j / 40u) * 32u); }
}

// ---------------- K1: histogram only (no key store) ----------------
__global__ void k1_hist(const float* __restrict__ cls, const float* __restrict__ obj) {
    int t4 = blockIdx.x * blockDim.x + threadIdx.x;
    if (t4 >= BATCH * NPRIOR / 4) return;
    int base = t4 * 4;
    int b = base / NPRIOR;           // NPRIOR % 4 == 0 -> all 4 in same batch
    float4 c = *(const float4*)(cls + base);
    float4 o = *(const float4*)(obj + base);
    float sv[4] = {sqrtf(c.x * o.x), sqrtf(c.y * o.y), sqrtf(c.z * o.z), sqrtf(c.w * o.w)};
#pragma unroll
    for (int j = 0; j < 4; j++)
        if (sv[j] > CONF_TH) atomicAdd(&g_hist[b * NB + bin_of(sv[j])], 1);
}

// ---------------- K2: suffix scan + cutoff; re-zeros g_hist ----------------
__global__ __launch_bounds__(1024, 1) void k2_scan() {
    __shared__ int suf[NB];
    __shared__ int wsum[32];
    __shared__ int sh_cb;
    const int b = blockIdx.x, tid = threadIdx.x;
    const int lane = tid & 31, warp = tid >> 5;
    if (tid == 0) sh_cb = 0;
    __syncthreads();

    int rbase = tid * 4;
    int v[4];
#pragma unroll
    for (int j = 0; j < 4; j++) v[j] = g_hist[b * NB + (NB - 1 - (rbase + j))];
    v[1] += v[0]; v[2] += v[1]; v[3] += v[2];
    int tot = v[3];
#pragma unroll
    for (int o = 1; o < 32; o <<= 1) {
        int n = __shfl_up_sync(0xffffffffu, tot, o);
        if (lane >= o) tot += n;
    }
    if (lane == 31) wsum[warp] = tot;
    __syncthreads();
    if (warp == 0) {
        int w = wsum[lane];
#pragma unroll
        for (int o = 1; o < 32; o <<= 1) {
            int n = __shfl_up_sync(0xffffffffu, w, o);
            if (lane >= o) w += n;
        }
        wsum[lane] = w;
    }
    __syncthreads();
    int pre = (warp ? wsum[warp - 1] : 0) + (tot - v[3]);
#pragma unroll
    for (int j = 0; j < 4; j++) suf[NB - 1 - (rbase + j)] = pre + v[j];
    __syncthreads();
    if (tid == 0) suf[0] = NPRIOR;
    __syncthreads();
    int local = -1;
#pragma unroll
    for (int j = 0; j < 4; j++) {
        int bin = NB - 1 - (rbase + j);
        if (bin >= 1 && suf[bin] >= TOPK && bin > local) local = bin;
    }
    if (local >= 0) atomicMax(&sh_cb, local);
    __syncthreads();
    int cb = sh_cb; if (cb < 1) cb = 1;
    int ctot = suf[cb]; if (ctot > CANDS) ctot = CANDS;
    if (tid == 0) {
        g_cb[b] = cb;
        g_ctot[b] = ctot;
        g_suf[b * (NB + 2) + NB] = 0;
        g_suf[b * (NB + 2) + NB + 1] = 0;
    }
    for (int i = tid; i < NB; i += 1024) {
        g_suf[b * (NB + 2) + i] = suf[i];
        g_bincur[b * NB + i] = 0;
        g_hist[b * NB + i] = 0;          // restore zero-invariant
    }
}

// ---------------- K3: recompute keys from cls/obj, scatter to g_cand ----------------
__global__ void k3_compact(const float* __restrict__ cls, const float* __restrict__ obj) {
    int t4 = blockIdx.x * blockDim.x + threadIdx.x;
    if (t4 >= BATCH * NPRIOR / 4) return;
    int base = t4 * 4;
    int b = base / NPRIOR;
    int i0 = base - b * NPRIOR;
    int cb = g_cb[b];
    float4 c = *(const float4*)(cls + base);
    float4 o = *(const float4*)(obj + base);
    float sv[4] = {sqrtf(c.x * o.x), sqrtf(c.y * o.y), sqrtf(c.z * o.z), sqrtf(c.w * o.w)};
#pragma unroll
    for (int j = 0; j < 4; j++) {
        float m = sv[j];
        if (!(m > CONF_TH)) continue;
        int bin = bin_of(m);
        if (bin < cb) continue;
        int pos = g_suf[b * (NB + 2) + bin + 1] + atomicAdd(&g_bincur[b * NB + bin], 1);
        if (pos < CANDS) {
            ull key = ((ull)key_from_float(m) << 32) | (unsigned)(~(unsigned)(i0 + j));
            g_cand[(size_t)b * CANDS + pos] = key;
        }
    }
}

// ---------------- K5: rank + decode + NMS + output (per-batch block) ----------------
#define OFF_SBOX   0                      // float4[5120] = 81920
#define OFF_SKEY   81920                  // ull[5120]    = 40960
#define OFF_SVAL   122880                 // u8[5120]     = 5120
#define OFF_COLBOX 128000                 // float4[3200] = 51200 ; cand ull[6144] overlays (49152)
#define OFF_CAND   128000
#define OFF_LARGE  179200                 // float4[256]  = 4096
#define OFF_KPOS   183296                 // u16[896]     = 1792
#define OFF_KEEPF  185088                 // u8[5000]     = 5000
#define SMEM_K5    190088

extern __shared__ char smem[];

__global__ __launch_bounds__(1024, 1)
void k5_nms(const float* __restrict__ bbox, const float* __restrict__ kps,
            float* __restrict__ out, int write_valid) {
    float4* sbox  = (float4*)(smem + OFF_SBOX);
    ull*    skey  = (ull*)   (smem + OFF_SKEY);
    unsigned char* svalid = (unsigned char*)(smem + OFF_SVAL);
    ull*    cand  = (ull*)   (smem + OFF_CAND);     // dead after rank phase
    float4* colbox= (float4*)(smem + OFF_COLBOX);   // overlays cand; live in NMS
    float4* large = (float4*)(smem + OFF_LARGE);
    unsigned short* kpos = (unsigned short*)(smem + OFF_KPOS);
    unsigned char*  keepf= (unsigned char*) (smem + OFF_KEEPF);

    __shared__ int wsum[32];
    __shared__ ull ovLoS[128];
    __shared__ ull ovHiS[128];
    __shared__ unsigned char statS[128];
    __shared__ int keptCount;
    __shared__ int colcnt[NCOL];
    __shared__ int lcnt;

    const int b = blockIdx.x, tid = threadIdx.x;
    const int lane = tid & 31, warp = tid >> 5;
    const size_t boff = (size_t)b * NPRIOR;
    const int ctot = g_ctot[b];
    const int* suf = g_suf + b * (NB + 2);

    // ---- load candidates into smem; zero tails ----
    for (int i = tid; i < ctot; i += 1024) cand[i] = g_cand[(size_t)b * CANDS + i];
    int fill0 = ctot < TOPK ? ctot : TOPK;
    for (int r = fill0 + tid; r < SPAD; r += 1024) {
        sbox[r] = make_float4(0.f, 0.f, 0.f, 0.f);
        svalid[r] = 0;
    }
    for (int r = fill0 + tid; r < TOPK; r += 1024) skey[r] = 0ull;
    for (int i = tid; i < TOPK; i += 1024) keepf[i] = 0;
    if (tid == 0) { keptCount = 0; lcnt = 0; }
    if (tid < NCOL) colcnt[tid] = 0;
    __syncthreads();

    // ---- rank (exact, in-bin) + decode boxes into smem ----
    for (int s = tid; s < ctot; s += 1024) {
        ull key = cand[s];
        float m = float_from_key((unsigned)(key >> 32));
        int bin = bin_of(m);
        int st = suf[bin + 1];
        int en = suf[bin]; if (en > ctot) en = ctot;
        int r = st;
        for (int q = st; q < en; q++)
            if (cand[q] > key) r++;
        if (r >= TOPK) continue;
        skey[r] = key;
        svalid[r] = ((unsigned)(key >> 32)) > KEYTH;
        unsigned idx = ~(unsigned)key;
        float px, py, ps; prior_of(idx, px, py, ps);
        const float* bb = bbox + (boff + idx) * 4;
        float cx = px + bb[0] * ps;
        float cy = py + bb[1] * ps;
        float w  = ps * expf(bb[2]);
        float h  = ps * expf(bb[3]);
        float x1 = cx - w * 0.5f, y1 = cy - h * 0.5f;
        sbox[r] = make_float4(x1, x1 + w, y1, y1 + h);
    }
    __syncthreads();   // cand dead -> colbox region reusable

    // ---- NMS: 128-wide chunks ----
    for (int base = 0; base < TOPK; base += 128) {
#pragma unroll
        for (int q = 0; q < 4; q++) {
            const int ci = q * 32 + warp;
            const int p = base + ci;
            float4 bj = sbox[p];
            float aj = (bj.y - bj.x) * (bj.w - bj.z);
            unsigned m0 = 0, m1 = 0, m2 = 0, m3 = 0;
            for (int q2 = 0; q2 <= q; q2++) {
                bool ob;
                if (q2 < q) ob = pair_sup(sbox[base + q2 * 32 + lane], bj, aj);
                else        ob = (lane < warp) ? pair_sup(sbox[base + q * 32 + lane], bj, aj) : false;
                unsigned bal = __ballot_sync(0xffffffffu, ob);
                if (q2 == 0) m0 = bal; else if (q2 == 1) m1 = bal;
                else if (q2 == 2) m2 = bal; else m3 = bal;
            }
            bool sup = false;
            int c0 = colclamp(bj.x), c1 = colclamp(bj.y);
            for (int c = c0; c <= c1; c++) {
                int n = colcnt[c];
                const float4* cp = colbox + c * COLCAP;
                for (int m = lane; m < n; m += 32)
                    sup |= pair_sup(cp[m], bj, aj);
            }
            {
                int n = lcnt;
                for (int m = lane; m < n; m += 32)
                    sup |= pair_sup(large[m], bj, aj);
            }
            sup = __any_sync(0xffffffffu, sup);
            if (lane == 0) {
                ovLoS[ci] = (ull)m0 | ((ull)m1 << 32);
                ovHiS[ci] = (ull)m2 | ((ull)m3 << 32);
                statS[ci] = (svalid[p] && !sup) ? 1 : 0;
            }
        }
        __syncthreads();

        if (warp == 0) {
            unsigned s0 = __ballot_sync(0xffffffffu, statS[lane]);
            unsigned s1 = __ballot_sync(0xffffffffu, statS[32 + lane]);
            unsigned s2 = __ballot_sync(0xffffffffu, statS[64 + lane]);
            unsigned s3 = __ballot_sync(0xffffffffu, statS[96 + lane]);
            ull aliveLo = (ull)s0 | ((ull)s1 << 32);
            ull aliveHi = (ull)s2 | ((ull)s3 << 32);
            bool cf0, cf1, cf2, cf3;
            {
                int i0 = lane, i1 = 32 + lane, i2 = 64 + lane, i3 = 96 + lane;
                cf0 = ((aliveLo >> i0) & 1ull) && ((ovLoS[i0] & aliveLo) | (ovHiS[i0] & aliveHi));
                cf1 = ((aliveLo >> i1) & 1ull) && ((ovLoS[i1] & aliveLo) | (ovHiS[i1] & aliveHi));
                cf2 = ((aliveHi >> (i2 - 64)) & 1ull) && ((ovLoS[i2] & aliveLo) | (ovHiS[i2] & aliveHi));
                cf3 = ((aliveHi >> (i3 - 64)) & 1ull) && ((ovLoS[i3] & aliveLo) | (ovHiS[i3] & aliveHi));
            }
            unsigned c0b = __ballot_sync(0xffffffffu, cf0);
            unsigned c1b = __ballot_sync(0xffffffffu, cf1);
            unsigned c2b = __ballot_sync(0xffffffffu, cf2);
            unsigned c3b = __ballot_sync(0xffffffffu, cf3);
            ull confLo = (ull)c0b | ((ull)c1b << 32);
            ull confHi = (ull)c2b | ((ull)c3b << 32);
            ull keepLo = aliveLo & ~confLo;
            ull keepHi = aliveHi & ~confHi;
            ull pLo = confLo, pHi = confHi;
            while (pLo | pHi) {
                int i;
                if (pLo) { i = __ffsll((long long)pLo) - 1; pLo &= pLo - 1; }
                else     { i = 64 + __ffsll((long long)pHi) - 1; pHi &= pHi - 1; }
                if (((ovLoS[i] & keepLo) | (ovHiS[i] & keepHi)) == 0ull) {
                    if (i < 64) keepLo |= 1ull << i; else keepHi |= 1ull << (i - 64);
                }
            }
            int b0 = keptCount;
            int totalKeep = __popcll(keepLo) + __popcll(keepHi);
            int nLo = __popcll(keepLo);
#pragma unroll
            for (int k = 0; k < 4; k++) {
                int ci = k * 32 + lane;
                int p = base + ci;
                bool kk = (ci < 64) ? ((keepLo >> ci) & 1ull) : ((keepHi >> (ci - 64)) & 1ull);
                if (p < TOPK) keepf[p] = kk ? 1 : 0;
                if (kk) {
                    int off = (ci < 64) ? __popcll(keepLo & ((1ull << ci) - 1ull))
                                        : nLo + __popcll(keepHi & ((1ull << (ci - 64)) - 1ull));
                    kpos[b0 + off] = (unsigned short)p;
                    float4 bl = sbox[p];
                    int cc0 = colclamp(bl.x), cc1 = colclamp(bl.y);
                    if (cc1 - cc0 >= 3) {
                        int d = atomicAdd(&lcnt, 1);
                        if (d < LARGECAP) large[d] = bl;
                    } else {
                        for (int c = cc0; c <= cc1; c++) {
                            int d = atomicAdd(&colcnt[c], 1);
                            if (d < COLCAP) colbox[c * COLCAP + d] = bl;
                            else { int e = atomicAdd(&lcnt, 1); if (e < LARGECAP) large[e] = bl; }
                        }
                    }
                }
            }
            if (lane == 0) keptCount = b0 + totalKeep;
        }
        __syncthreads();
        if (keptCount >= KEEPK) break;
    }
    __syncthreads();

    int kc = keptCount;
    int kout = kc < KEEPK ? kc : KEEPK;

    // parallel filler: first (KEEPK-kc) non-kept positions, in order
    if (kc < KEEPK) {
        int need = KEEPK - kc;
        int j0 = tid * 5;
        int cnt = 0;
#pragma unroll
        for (int j = 0; j < 5; j++) {
            int p = j0 + j;
            if (p < TOPK && !keepf[p]) cnt++;
        }
        int x = cnt;
#pragma unroll
        for (int o = 1; o < 32; o <<= 1) {
            int n = __shfl_up_sync(0xffffffffu, x, o);
            if (lane >= o) x += n;
        }
        if (lane == 31) wsum[warp] = x;
        __syncthreads();
        if (warp == 0) {
            int w = wsum[lane];
#pragma unroll
            for (int o = 1; o < 32; o <<= 1) {
                int n = __shfl_up_sync(0xffffffffu, w, o);
                if (lane >= o) w += n;
            }
            wsum[lane] = w;
        }
        __syncthreads();
        int pre = (warp ? wsum[warp - 1] : 0) + (x - cnt);
#pragma unroll
        for (int j = 0; j < 5; j++) {
            int p = j0 + j;
            if (p < TOPK && !keepf[p]) {
                if (pre < need) kpos[kc + pre] = (unsigned short)p;
                pre++;
            }
        }
    }
    __syncthreads();

    // write final 750 rows
    for (int r = tid; r < KEEPK; r += 1024) {
        int pos = kpos[r];
        ull key = skey[pos];
        unsigned idx = ~(unsigned)key;
        unsigned hk = (unsigned)(key >> 32);
        float score = __uint_as_float((hk & 0x80000000u) ? (hk ^ 0x80000000u) : ~hk);
        float px, py, ps; prior_of(idx, px, py, ps);
        const float* bb = bbox + (boff + idx) * 4;
        float cx = px + bb[0] * ps, cy = py + bb[1] * ps;
        float w = ps * expf(bb[2]), h = ps * expf(bb[3]);
        float x1 = cx - w * 0.5f, y1 = cy - h * 0.5f;
        size_t t = (size_t)b * KEEPK + r;
        float* o = out + t * 15;
        o[0] = x1; o[1] = y1; o[2] = x1 + w; o[3] = y1 + h;
        const float* kp = kps + (boff + idx) * 10;
#pragma unroll
        for (int m = 0; m < 5; m++) {
            o[4 + 2 * m] = px + kp[2 * m] * ps;
            o[5 + 2 * m] = py + kp[2 * m + 1] * ps;
        }
        o[14] = score;
        if (write_valid)
            out[(size_t)BATCH * KEEPK * 15 + t] = (r < kout) ? 1.0f : 0.0f;
    }
}

// ---------------- launch ----------------
extern "C" void kernel_launch(void* const* d_in, const int* in_sizes, int n_in,
                              void* d_out, int out_size) {
    const float* cls  = (const float*)d_in[0];
    const float* obj  = (const float*)d_in[1];
    const float* bbox = (const float*)d_in[2];
    const float* kps  = (const float*)d_in[3];
    float* out = (float*)d_out;

    static int attr_set = 0;
    if (!attr_set) {
        cudaFuncSetAttribute(k5_nms, cudaFuncAttributeMaxDynamicSharedMemorySize, SMEM_K5);
        attr_set = 1;
    }

    k1_hist<<<(BATCH * NPRIOR / 4 + 255) / 256, 256>>>(cls, obj);
    k2_scan<<<BATCH, 1024>>>();
    k3_compact<<<(BATCH * NPRIOR / 4 + 255) / 256, 256>>>(cls, obj);

    int write_valid = (out_size >= BATCH * KEEPK * 16) ? 1 : 0;
    k5_nms<<<BATCH, 1024, SMEM_K5>>>(bbox, kps, out, write_valid);
}

// round 12
// speedup vs baseline: 1.0227x; 1.0227x over previous
#include <cuda_runtime.h>
#include <stdint.h>

#define BATCH   8
#define NPRIOR  33600
#define TOPK    5000
#define KEEPK   750
#define CONF_TH 0.3f
#define NMS_TH  0.3f
#define NB      4096
#define CANDS   6144
#define BINSCALE (4094.0f / 0.7f)
#define KEYTH   0xBE99999Au     // key_from_float(0.3f)

#define NCOL    20
#define COLCAP  160
#define LARGECAP 256
#define INVCOLW (1.0f / 64.0f)
#define SPAD    5120            // TOPK padded to chunk multiple (128)

#define NBLK    128
#define NTHR    1024

typedef unsigned long long ull;

// ---------------- device scratch ----------------
__device__ int    g_hist[BATCH * NB];        // zero at load; every pass restores zero
__device__ int    g_bincur[BATCH * NB];
__device__ int    g_suf[BATCH * (NB + 2)];
__device__ int    g_cb[BATCH];
__device__ int    g_ctot[BATCH];
__device__ ull    g_cand[(size_t)BATCH * CANDS];
__device__ ull    g_top [(size_t)BATCH * TOPK];
__device__ float4 g_boxes[(size_t)BATCH * TOPK];
__device__ unsigned g_count;                 // grid barrier state; reset at end of launch
__device__ unsigned g_flag;

// ---------------- helpers ----------------
__device__ __forceinline__ unsigned key_from_float(float f) {
    unsigned u = __float_as_uint(f);
    return (u & 0x80000000u) ? ~u : (u | 0x80000000u);
}
__device__ __forceinline__ float float_from_key(unsigned u) {
    return __uint_as_float((u & 0x80000000u) ? (u ^ 0x80000000u) : ~u);
}
__device__ __forceinline__ int bin_of(float m) {
    if (!(m > CONF_TH)) return 0;
    int b = (int)((m - CONF_TH) * BINSCALE);
    if (b > 4094) b = 4094;
    return 1 + b;
}
__device__ __forceinline__ int colclamp(float x) {
    int c = (int)floorf(x * INVCOLW);
    return c < 0 ? 0 : (c > NCOL - 1 ? NCOL - 1 : c);
}
// box = (x1,x2,y1,y2); w,h>0 so reference clamps are identity; division exact
__device__ __forceinline__ bool pair_sup(float4 a, float4 b, float ab) {
    float xo = fminf(a.y, b.y) - fmaxf(a.x, b.x);
    float yo = fminf(a.w, b.w) - fmaxf(a.z, b.z);
    if (xo > 0.0f && yo > 0.0f) {
        float inter = xo * yo;
        float aa = (a.y - a.x) * (a.w - a.z);
        return inter / (aa + ab - inter + 1e-12f) > NMS_TH;
    }
    return false;
}
__device__ __forceinline__ void prior_of(unsigned idx, float& px, float& py, float& ps) {
    if (idx < 25600u)      { ps = 8.0f;  px = (float)((idx % 160u) * 8u); py = (float)((idx / 160u) * 8u); }
    else if (idx < 32000u) { unsigned j = idx - 25600u; ps = 16.0f; px = (float)((j % 80u) * 16u); py = (float)((j / 80u) * 16u); }
    else                   { unsigned j = idx - 32000u; ps = 32.0f; px = (float)((j % 40u) * 32u); py = (float)((j / 40u) * 32u); }
}

// grid barrier: monotonic count + release flag. All NBLK blocks co-resident
// (1 block/SM via 190KB smem, NBLK=128 <= SM count) -> no deadlock.
__device__ __forceinline__ void grid_bar(int k) {
    __syncthreads();
    if (threadIdx.x == 0) {
        __threadfence();
        unsigned v = atomicAdd(&g_count, 1u) + 1u;
        if (v == (unsigned)(k * NBLK)) {
            atomicExch(&g_flag, (unsigned)k);
        } else {
            while (atomicAdd(&g_flag, 0u) < (unsigned)k) __nanosleep(64);
        }
        __threadfence();
    }
    __syncthreads();
}

// ---- dynamic shared layout (bytes) — NMS phase; scan phase reuses region 0 ----
#define OFF_SBOX   0                      // float4[5120] = 81920 ; scan int[4096] overlays
#define OFF_SVAL   81920                  // u8[5120]     = 5120
#define OFF_COLBOX 87040                  // float4[20*160] = 51200
#define OFF_LARGE  138240                 // float4[256]  = 4096
#define OFF_KPOS   142336                 // u16[896]     = 1792
#define OFF_KEEPF  144128                 // u8[5000]     = 5000
#define SMEM_ALL   149128

extern __shared__ char smem[];

__global__ __launch_bounds__(NTHR, 1)
void fused_all(const float* __restrict__ cls, const float* __restrict__ obj,
               const float* __restrict__ bbox, const float* __restrict__ kps,
               float* __restrict__ out, int write_valid) {
    const int tid = threadIdx.x;
    const int lane = tid & 31, warp = tid >> 5;
    __shared__ int wsum[32];
    __shared__ int sh_cb;

    // ================= Phase A: histogram (all blocks) =================
    for (int t4 = blockIdx.x * NTHR + tid; t4 < BATCH * NPRIOR / 4; t4 += NBLK * NTHR) {
        int base = t4 * 4;
        int b = base / NPRIOR;          // NPRIOR % 4 == 0 -> all 4 in same batch
        float4 c = *(const float4*)(cls + base);
        float4 o = *(const float4*)(obj + base);
        float sv[4] = {sqrtf(c.x * o.x), sqrtf(c.y * o.y), sqrtf(c.z * o.z), sqrtf(c.w * o.w)};
#pragma unroll
        for (int j = 0; j < 4; j++)
            if (sv[j] > CONF_TH) atomicAdd(&g_hist[b * NB + bin_of(sv[j])], 1);
    }
    grid_bar(1);

    // ================= Phase B: suffix scan + cutoff (blocks 0..7) =================
    if (blockIdx.x < BATCH) {
        int* suf = (int*)(smem + OFF_SBOX);          // overlay; NMS data not yet live
        const int b = blockIdx.x;
        if (tid == 0) sh_cb = 0;
        __syncthreads();
        int rbase = tid * 4;
        int v[4];
#pragma unroll
        for (int j = 0; j < 4; j++) v[j] = g_hist[b * NB + (NB - 1 - (rbase + j))];
        v[1] += v[0]; v[2] += v[1]; v[3] += v[2];
        int tot = v[3];
#pragma unroll
        for (int o = 1; o < 32; o <<= 1) {
            int n = __shfl_up_sync(0xffffffffu, tot, o);
            if (lane >= o) tot += n;
        }
        if (lane == 31) wsum[warp] = tot;
        __syncthreads();
        if (warp == 0) {
            int w = wsum[lane];
#pragma unroll
            for (int o = 1; o < 32; o <<= 1) {
                int n = __shfl_up_sync(0xffffffffu, w, o);
                if (lane >= o) w += n;
            }
            wsum[lane] = w;
        }
        __syncthreads();
        int pre = (warp ? wsum[warp - 1] : 0) + (tot - v[3]);
#pragma unroll
        for (int j = 0; j < 4; j++) suf[NB - 1 - (rbase + j)] = pre + v[j];
        __syncthreads();
        if (tid == 0) suf[0] = NPRIOR;
        __syncthreads();
        int local = -1;
#pragma unroll
        for (int j = 0; j < 4; j++) {
            int bin = NB - 1 - (rbase + j);
            if (bin >= 1 && suf[bin] >= TOPK && bin > local) local = bin;
        }
        if (local >= 0) atomicMax(&sh_cb, local);
        __syncthreads();
        int cb = sh_cb; if (cb < 1) cb = 1;
        int ctot = suf[cb]; if (ctot > CANDS) ctot = CANDS;
        if (tid == 0) {
            g_cb[b] = cb;
            g_ctot[b] = ctot;
            g_suf[b * (NB + 2) + NB] = 0;
            g_suf[b * (NB + 2) + NB + 1] = 0;
        }
        for (int i = tid; i < NB; i += NTHR) {
            g_suf[b * (NB + 2) + i] = suf[i];
            g_bincur[b * NB + i] = 0;
            g_hist[b * NB + i] = 0;      // restore zero-invariant for next launch
        }
        for (int r = ctot + tid; r < TOPK; r += NTHR) {
            g_top[(size_t)b * TOPK + r] = 0ull;
            g_boxes[(size_t)b * TOPK + r] = make_float4(0.f, 0.f, 0.f, 0.f);
        }
    }
    grid_bar(2);

    // ================= Phase C: compact (all blocks; recompute keys) =================
    for (int t4 = blockIdx.x * NTHR + tid; t4 < BATCH * NPRIOR / 4; t4 += NBLK * NTHR) {
        int base = t4 * 4;
        int b = base / NPRIOR;
        int i0 = base - b * NPRIOR;
        int cb = g_cb[b];
        float4 c = *(const float4*)(cls + base);
        float4 o = *(const float4*)(obj + base);
        float sv[4] = {sqrtf(c.x * o.x), sqrtf(c.y * o.y), sqrtf(c.z * o.z), sqrtf(c.w * o.w)};
#pragma unroll
        for (int j = 0; j < 4; j++) {
            float m = sv[j];
            if (!(m > CONF_TH)) continue;
            int bin = bin_of(m);
            if (bin < cb) continue;
            int pos = g_suf[b * (NB + 2) + bin + 1] + atomicAdd(&g_bincur[b * NB + bin], 1);
            if (pos < CANDS) {
                ull key = ((ull)key_from_float(m) << 32) | (unsigned)(~(unsigned)(i0 + j));
                g_cand[(size_t)b * CANDS + pos] = key;
            }
        }
    }
    grid_bar(3);

    // ================= Phase D: exact in-bin rank + decode (all blocks) =================
    for (int t = blockIdx.x * NTHR + tid; t < BATCH * CANDS; t += NBLK * NTHR) {
        int b = t / CANDS;
        int s = t - b * CANDS;
        int ct = g_ctot[b];
        if (s >= ct) continue;
        const ull* cand = g_cand + (size_t)b * CANDS;
        ull key = cand[s];
        float m = float_from_key((unsigned)(key >> 32));
        int bin = bin_of(m);
        const int* suf = g_suf + b * (NB + 2);
        int st = suf[bin + 1];
        int en = suf[bin]; if (en > ct) en = ct;
        int r = st;
        for (int q = st; q < en; q++)
            if (cand[q] > key) r++;
        if (r >= TOPK) continue;
        g_top[(size_t)b * TOPK + r] = key;
        unsigned idx = ~(unsigned)key;
        float px, py, ps; prior_of(idx, px, py, ps);
        const float* bb = bbox + ((size_t)b * NPRIOR + idx) * 4;
        float cx = px + bb[0] * ps;
        float cy = py + bb[1] * ps;
        float w  = ps * expf(bb[2]);
        float h  = ps * expf(bb[3]);
        float x1 = cx - w * 0.5f, y1 = cy - h * 0.5f;
        g_boxes[(size_t)b * TOPK + r] = make_float4(x1, x1 + w, y1, y1 + h);
    }
    grid_bar(4);

    // ================= Phase E: NMS + filler + output (blocks 0..7) =================
    if (blockIdx.x >= BATCH) return;
    {
        float4* sbox  = (float4*)(smem + OFF_SBOX);
        unsigned char* svalid = (unsigned char*)(smem + OFF_SVAL);
        float4* colbox= (float4*)(smem + OFF_COLBOX);
        float4* large = (float4*)(smem + OFF_LARGE);
        unsigned short* kpos = (unsigned short*)(smem + OFF_KPOS);
        unsigned char*  keepf= (unsigned char*) (smem + OFF_KEEPF);

        __shared__ ull ovLoS[128];
        __shared__ ull ovHiS[128];
        __shared__ unsigned char statS[128];
        __shared__ int keptCount;
        __shared__ int colcnt[NCOL];
        __shared__ int lcnt;

        const int b = blockIdx.x;
        const size_t bT = (size_t)b * TOPK;
        const size_t boff = (size_t)b * NPRIOR;

        __syncthreads();   // phase-B suf overlay fully dead before sbox writes
        for (int i = tid; i < TOPK; i += NTHR) {
            sbox[i] = g_boxes[bT + i];
            svalid[i] = ((unsigned)(g_top[bT + i] >> 32)) > KEYTH;
            keepf[i] = 0;
        }
        for (int i = TOPK + tid; i < SPAD; i += NTHR) {
            sbox[i] = make_float4(0.f, 0.f, 0.f, 0.f);
            svalid[i] = 0;
        }
        if (tid == 0) { keptCount = 0; lcnt = 0; }
        if (tid < NCOL) colcnt[tid] = 0;
        __syncthreads();

        for (int base = 0; base < TOPK; base += 128) {
#pragma unroll
            for (int q = 0; q < 4; q++) {
                const int ci = q * 32 + warp;
                const int p = base + ci;
                float4 bj = sbox[p];
                float aj = (bj.y - bj.x) * (bj.w - bj.z);
                unsigned m0 = 0, m1 = 0, m2 = 0, m3 = 0;
                for (int q2 = 0; q2 <= q; q2++) {
                    bool ob;
                    if (q2 < q) ob = pair_sup(sbox[base + q2 * 32 + lane], bj, aj);
                    else        ob = (lane < warp) ? pair_sup(sbox[base + q * 32 + lane], bj, aj) : false;
                    unsigned bal = __ballot_sync(0xffffffffu, ob);
                    if (q2 == 0) m0 = bal; else if (q2 == 1) m1 = bal;
                    else if (q2 == 2) m2 = bal; else m3 = bal;
                }
                bool sup = false;
                int c0 = colclamp(bj.x), c1 = colclamp(bj.y);
                for (int c = c0; c <= c1; c++) {
                    int n = colcnt[c];
                    const float4* cp = colbox + c * COLCAP;
                    for (int m = lane; m < n; m += 32)
                        sup |= pair_sup(cp[m], bj, aj);
                }
                {
                    int n = lcnt;
                    for (int m = lane; m < n; m += 32)
                        sup |= pair_sup(large[m], bj, aj);
                }
                sup = __any_sync(0xffffffffu, sup);
                if (lane == 0) {
                    ovLoS[ci] = (ull)m0 | ((ull)m1 << 32);
                    ovHiS[ci] = (ull)m2 | ((ull)m3 << 32);
                    statS[ci] = (svalid[p] && !sup) ? 1 : 0;
                }
            }
            __syncthreads();

            if (warp == 0) {
                unsigned s0 = __ballot_sync(0xffffffffu, statS[lane]);
                unsigned s1 = __ballot_sync(0xffffffffu, statS[32 + lane]);
                unsigned s2 = __ballot_sync(0xffffffffu, statS[64 + lane]);
                unsigned s3 = __ballot_sync(0xffffffffu, statS[96 + lane]);
                ull aliveLo = (ull)s0 | ((ull)s1 << 32);
                ull aliveHi = (ull)s2 | ((ull)s3 << 32);
                bool cf0, cf1, cf2, cf3;
                {
                    int i0 = lane, i1 = 32 + lane, i2 = 64 + lane, i3 = 96 + lane;
                    cf0 = ((aliveLo >> i0) & 1ull) && ((ovLoS[i0] & aliveLo) | (ovHiS[i0] & aliveHi));
                    cf1 = ((aliveLo >> i1) & 1ull) && ((ovLoS[i1] & aliveLo) | (ovHiS[i1] & aliveHi));
                    cf2 = ((aliveHi >> (i2 - 64)) & 1ull) && ((ovLoS[i2] & aliveLo) | (ovHiS[i2] & aliveHi));
                    cf3 = ((aliveHi >> (i3 - 64)) & 1ull) && ((ovLoS[i3] & aliveLo) | (ovHiS[i3] & aliveHi));
                }
                unsigned c0b = __ballot_sync(0xffffffffu, cf0);
                unsigned c1b = __ballot_sync(0xffffffffu, cf1);
                unsigned c2b = __ballot_sync(0xffffffffu, cf2);
                unsigned c3b = __ballot_sync(0xffffffffu, cf3);
                ull confLo = (ull)c0b | ((ull)c1b << 32);
                ull confHi = (ull)c2b | ((ull)c3b << 32);
                ull keepLo = aliveLo & ~confLo;
                ull keepHi = aliveHi & ~confHi;
                ull pLo = confLo, pHi = confHi;
                while (pLo | pHi) {
                    int i;
                    if (pLo) { i = __ffsll((long long)pLo) - 1; pLo &= pLo - 1; }
                    else     { i = 64 + __ffsll((long long)pHi) - 1; pHi &= pHi - 1; }
                    if (((ovLoS[i] & keepLo) | (ovHiS[i] & keepHi)) == 0ull) {
                        if (i < 64) keepLo |= 1ull << i; else keepHi |= 1ull << (i - 64);
                    }
                }
                int b0 = keptCount;
                int totalKeep = __popcll(keepLo) + __popcll(keepHi);
                int nLo = __popcll(keepLo);
#pragma unroll
                for (int k = 0; k < 4; k++) {
                    int ci = k * 32 + lane;
                    int p = base + ci;
                    bool kk = (ci < 64) ? ((keepLo >> ci) & 1ull) : ((keepHi >> (ci - 64)) & 1ull);
                    if (p < TOPK) keepf[p] = kk ? 1 : 0;
                    if (kk) {
                        int off = (ci < 64) ? __popcll(keepLo & ((1ull << ci) - 1ull))
                                            : nLo + __popcll(keepHi & ((1ull << (ci - 64)) - 1ull));
                        kpos[b0 + off] = (unsigned short)p;
                        float4 bl = sbox[p];
                        int cc0 = colclamp(bl.x), cc1 = colclamp(bl.y);
                        if (cc1 - cc0 >= 3) {
                            int d = atomicAdd(&lcnt, 1);
                            if (d < LARGECAP) large[d] = bl;
                        } else {
                            for (int c = cc0; c <= cc1; c++) {
                                int d = atomicAdd(&colcnt[c], 1);
                                if (d < COLCAP) colbox[c * COLCAP + d] = bl;
                                else { int e = atomicAdd(&lcnt, 1); if (e < LARGECAP) large[e] = bl; }
                            }
                        }
                    }
                }
                if (lane == 0) keptCount = b0 + totalKeep;
            }
            __syncthreads();
            if (keptCount >= KEEPK) break;
        }
        __syncthreads();

        int kc = keptCount;
        int kout = kc < KEEPK ? kc : KEEPK;

        // parallel filler: first (KEEPK-kc) non-kept positions, in order
        if (kc < KEEPK) {
            int need = KEEPK - kc;
            int j0 = tid * 5;
            int cnt = 0;
#pragma unroll
            for (int j = 0; j < 5; j++) {
                int p = j0 + j;
                if (p < TOPK && !keepf[p]) cnt++;
            }
            int x = cnt;
#pragma unroll
            for (int o = 1; o < 32; o <<= 1) {
                int n = __shfl_up_sync(0xffffffffu, x, o);
                if (lane >= o) x += n;
            }
            if (lane == 31) wsum[warp] = x;
            __syncthreads();
            if (warp == 0) {
                int w = wsum[lane];
#pragma unroll
                for (int o = 1; o < 32; o <<= 1) {
                    int n = __shfl_up_sync(0xffffffffu, w, o);
                    if (lane >= o) w += n;
                }
                wsum[lane] = w;
            }
            __syncthreads();
            int pre = (warp ? wsum[warp - 1] : 0) + (x - cnt);
#pragma unroll
            for (int j = 0; j < 5; j++) {
                int p = j0 + j;
                if (p < TOPK && !keepf[p]) {
                    if (pre < need) kpos[kc + pre] = (unsigned short)p;
                    pre++;
                }
            }
        }
        __syncthreads();

        // write final 750 rows
        for (int r = tid; r < KEEPK; r += NTHR) {
            int pos = kpos[r];
            ull key = g_top[bT + pos];
            unsigned idx = ~(unsigned)key;
            unsigned hk = (unsigned)(key >> 32);
            float score = __uint_as_float((hk & 0x80000000u) ? (hk ^ 0x80000000u) : ~hk);
            float px, py, ps; prior_of(idx, px, py, ps);
            const float* bb = bbox + (boff + idx) * 4;
            float cx = px + bb[0] * ps, cy = py + bb[1] * ps;
            float w = ps * expf(bb[2]), h = ps * expf(bb[3]);
            float x1 = cx - w * 0.5f, y1 = cy - h * 0.5f;
            size_t t = (size_t)b * KEEPK + r;
            float* o = out + t * 15;
            o[0] = x1; o[1] = y1; o[2] = x1 + w; o[3] = y1 + h;
            const float* kp = kps + (boff + idx) * 10;
#pragma unroll
            for (int m = 0; m < 5; m++) {
                o[4 + 2 * m] = px + kp[2 * m] * ps;
                o[5 + 2 * m] = py + kp[2 * m + 1] * ps;
            }
            o[14] = score;
            if (write_valid)
                out[(size_t)BATCH * KEEPK * 15 + t] = (r < kout) ? 1.0f : 0.0f;
        }

        // reset barrier state for next launch/replay. All spinners exited
        // within ~1us of the last release; this runs ~30us later (after NMS).
        __syncthreads();
        if (blockIdx.x == 0 && tid == 0) {
            atomicExch(&g_count, 0u);
            atomicExch(&g_flag, 0u);
        }
    }
}

// ---------------- launch ----------------
extern "C" void kernel_launch(void* const* d_in, const int* in_sizes, int n_in,
                              void* d_out, int out_size) {
    const float* cls  = (const float*)d_in[0];
    const float* obj  = (const float*)d_in[1];
    const float* bbox = (const float*)d_in[2];
    const float* kps  = (const float*)d_in[3];
    float* out = (float*)d_out;

    static int attr_set = 0;
    if (!attr_set) {
        cudaFuncSetAttribute(fused_all, cudaFuncAttributeMaxDynamicSharedMemorySize, SMEM_ALL);
        attr_set = 1;
    }
    int write_valid = (out_size >= BATCH * KEEPK * 16) ? 1 : 0;
    fused_all<<<NBLK, NTHR, SMEM_ALL>>>(cls, obj, bbox, kps, out, write_valid);
}

// round 13
// speedup vs baseline: 1.0951x; 1.0708x over previous
#include <cuda_runtime.h>
#include <stdint.h>

#define BATCH   8
#define NPRIOR  33600
#define TOPK    5000
#define KEEPK   750
#define CONF_TH 0.3f
#define NMS_TH  0.3f
#define NB      4096
#define CANDS   6144
#define BINSCALE (4094.0f / 0.7f)
#define KEYTH   0xBE99999Au     // key_from_float(0.3f)

#define NCOL    20
#define COLCAP  160
#define LARGECAP 256
#define INVCOLW (1.0f / 64.0f)
#define SPAD    5120            // TOPK padded to chunk multiple (128)

typedef unsigned long long ull;

// ---------------- device scratch ----------------
__device__ int    g_hist[BATCH * NB];        // zero at load; every pass restores zero
__device__ int    g_bincur[BATCH * NB];
__device__ int    g_suf[BATCH * (NB + 2)];
__device__ int    g_cb[BATCH];
__device__ int    g_ctot[BATCH];
__device__ ull    g_cand[(size_t)BATCH * CANDS];
__device__ ull    g_top [(size_t)BATCH * TOPK];
__device__ float4 g_boxes[(size_t)BATCH * TOPK];

// ---------------- helpers ----------------
__device__ __forceinline__ unsigned key_from_float(float f) {
    unsigned u = __float_as_uint(f);
    return (u & 0x80000000u) ? ~u : (u | 0x80000000u);
}
__device__ __forceinline__ float float_from_key(unsigned u) {
    return __uint_as_float((u & 0x80000000u) ? (u ^ 0x80000000u) : ~u);
}
__device__ __forceinline__ int bin_of(float m) {
    if (!(m > CONF_TH)) return 0;
    int b = (int)((m - CONF_TH) * BINSCALE);
    if (b > 4094) b = 4094;
    return 1 + b;
}
__device__ __forceinline__ int colclamp(float x) {
    int c = (int)floorf(x * INVCOLW);
    return c < 0 ? 0 : (c > NCOL - 1 ? NCOL - 1 : c);
}
// box = (x1,x2,y1,y2); w,h>0 so reference clamps are identity; division exact
__device__ __forceinline__ bool pair_sup(float4 a, float4 b, float ab) {
    float xo = fminf(a.y, b.y) - fmaxf(a.x, b.x);
    float yo = fminf(a.w, b.w) - fmaxf(a.z, b.z);
    if (xo > 0.0f && yo > 0.0f) {
        float inter = xo * yo;
        float aa = (a.y - a.x) * (a.w - a.z);
        return inter / (aa + ab - inter + 1e-12f) > NMS_TH;
    }
    return false;
}
__device__ __forceinline__ void prior_of(unsigned idx, float& px, float& py, float& ps) {
    if (idx < 25600u)      { ps = 8.0f;  px = (float)((idx % 160u) * 8u); py = (float)((idx / 160u) * 8u); }
    else if (idx < 32000u) { unsigned j = idx - 25600u; ps = 16.0f; px = (float)((j % 80u) * 16u); py = (float)((j / 80u) * 16u); }
    else                   { unsigned j = idx - 32000u; ps = 32.0f; px = (float)((j % 40u) * 32u); py = (float)((j / 40u) * 32u); }
}

// ---------------- K1: histogram only (no key store) ----------------
__global__ void k1_hist(const float* __restrict__ cls, const float* __restrict__ obj) {
    int t4 = blockIdx.x * blockDim.x + threadIdx.x;
    if (t4 >= BATCH * NPRIOR / 4) return;
    int base = t4 * 4;
    int b = base / NPRIOR;           // NPRIOR % 4 == 0 -> all 4 in same batch
    float4 c = *(const float4*)(cls + base);
    float4 o = *(const float4*)(obj + base);
    float sv[4] = {sqrtf(c.x * o.x), sqrtf(c.y * o.y), sqrtf(c.z * o.z), sqrtf(c.w * o.w)};
#pragma unroll
    for (int j = 0; j < 4; j++)
        if (sv[j] > CONF_TH) atomicAdd(&g_hist[b * NB + bin_of(sv[j])], 1);
}

// ---------------- K2: suffix scan + cutoff; re-zeros g_hist ----------------
__global__ __launch_bounds__(1024, 1) void k2_scan() {
    __shared__ int suf[NB];
    __shared__ int wsum[32];
    __shared__ int sh_cb;
    const int b = blockIdx.x, tid = threadIdx.x;
    const int lane = tid & 31, warp = tid >> 5;
    if (tid == 0) sh_cb = 0;
    __syncthreads();

    int rbase = tid * 4;
    int v[4];
#pragma unroll
    for (int j = 0; j < 4; j++) v[j] = g_hist[b * NB + (NB - 1 - (rbase + j))];
    v[1] += v[0]; v[2] += v[1]; v[3] += v[2];
    int tot = v[3];
#pragma unroll
    for (int o = 1; o < 32; o <<= 1) {
        int n = __shfl_up_sync(0xffffffffu, tot, o);
        if (lane >= o) tot += n;
    }
    if (lane == 31) wsum[warp] = tot;
    __syncthreads();
    if (warp == 0) {
        int w = wsum[lane];
#pragma unroll
        for (int o = 1; o < 32; o <<= 1) {
            int n = __shfl_up_sync(0xffffffffu, w, o);
            if (lane >= o) w += n;
        }
        wsum[lane] = w;
    }
    __syncthreads();
    int pre = (warp ? wsum[warp - 1] : 0) + (tot - v[3]);
#pragma unroll
    for (int j = 0; j < 4; j++) suf[NB - 1 - (rbase + j)] = pre + v[j];
    __syncthreads();
    if (tid == 0) suf[0] = NPRIOR;
    __syncthreads();
    int local = -1;
#pragma unroll
    for (int j = 0; j < 4; j++) {
        int bin = NB - 1 - (rbase + j);
        if (bin >= 1 && suf[bin] >= TOPK && bin > local) local = bin;
    }
    if (local >= 0) atomicMax(&sh_cb, local);
    __syncthreads();
    int cb = sh_cb; if (cb < 1) cb = 1;
    int ctot = suf[cb]; if (ctot > CANDS) ctot = CANDS;
    if (tid == 0) {
        g_cb[b] = cb;
        g_ctot[b] = ctot;
        g_suf[b * (NB + 2) + NB] = 0;
        g_suf[b * (NB + 2) + NB + 1] = 0;
    }
    for (int i = tid; i < NB; i += 1024) {
        g_suf[b * (NB + 2) + i] = suf[i];
        g_bincur[b * NB + i] = 0;
        g_hist[b * NB + i] = 0;          // restore zero-invariant
    }
    for (int r = ctot + tid; r < TOPK; r += 1024) {
        g_top[(size_t)b * TOPK + r] = 0ull;
        g_boxes[(size_t)b * TOPK + r] = make_float4(0.f, 0.f, 0.f, 0.f);
    }
}

// ---------------- K3: recompute keys from cls/obj, scatter to g_cand ----------------
__global__ void k3_compact(const float* __restrict__ cls, const float* __restrict__ obj) {
    int t4 = blockIdx.x * blockDim.x + threadIdx.x;
    if (t4 >= BATCH * NPRIOR / 4) return;
    int base = t4 * 4;
    int b = base / NPRIOR;
    int i0 = base - b * NPRIOR;
    int cb = g_cb[b];
    float4 c = *(const float4*)(cls + base);
    float4 o = *(const float4*)(obj + base);
    float sv[4] = {sqrtf(c.x * o.x), sqrtf(c.y * o.y), sqrtf(c.z * o.z), sqrtf(c.w * o.w)};
#pragma unroll
    for (int j = 0; j < 4; j++) {
        float m = sv[j];
        if (!(m > CONF_TH)) continue;
        int bin = bin_of(m);
        if (bin < cb) continue;
        int pos = g_suf[b * (NB + 2) + bin + 1] + atomicAdd(&g_bincur[b * NB + bin], 1);
        if (pos < CANDS) {
            ull key = ((ull)key_from_float(m) << 32) | (unsigned)(~(unsigned)(i0 + j));
            g_cand[(size_t)b * CANDS + pos] = key;
        }
    }
}

// ---------------- K4: exact in-bin rank + decode ----------------
__global__ void k4_rank(const float* __restrict__ bbox) {
    int t = blockIdx.x * blockDim.x + threadIdx.x;
    int b = t / CANDS;
    if (b >= BATCH) return;
    int s = t - b * CANDS;
    int ct = g_ctot[b];
    if (s >= ct) return;
    const ull* cand = g_cand + (size_t)b * CANDS;
    ull key = __ldg(cand + s);
    float m = float_from_key((unsigned)(key >> 32));
    int bin = bin_of(m);
    const int* suf = g_suf + b * (NB + 2);
    int st = suf[bin + 1];
    int en = suf[bin]; if (en > ct) en = ct;
    int r = st;
    for (int q = st; q < en; q++)
        if (__ldg(cand + q) > key) r++;
    if (r >= TOPK) return;
    g_top[(size_t)b * TOPK + r] = key;
    unsigned idx = ~(unsigned)key;
    float px, py, ps; prior_of(idx, px, py, ps);
    const float* bb = bbox + ((size_t)b * NPRIOR + idx) * 4;
    float cx = px + bb[0] * ps;
    float cy = py + bb[1] * ps;
    float w  = ps * expf(bb[2]);
    float h  = ps * expf(bb[3]);
    float x1 = cx - w * 0.5f, y1 = cy - h * 0.5f;
    g_boxes[(size_t)b * TOPK + r] = make_float4(x1, x1 + w, y1, y1 + h);
}

// ---------------- K5: NMS, 128-wide chunks, smem-resident boxes ----------------
#define OFF_SBOX   0                      // float4[5120] = 81920
#define OFF_SVAL   81920                  // u8[5120]     = 5120
#define OFF_COLBOX 87040                  // float4[20*160] = 51200
#define OFF_LARGE  138240                 // float4[256]  = 4096
#define OFF_KPOS   142336                 // u16[896]     = 1792
#define OFF_KEEPF  144128                 // u8[5000]     = 5000
#define SMEM_K5    149128

extern __shared__ char smem[];

__global__ __launch_bounds__(1024, 1)
void k5_nms(const float* __restrict__ bbox, const float* __restrict__ kps,
            float* __restrict__ out, int write_valid) {
    float4* sbox  = (float4*)(smem + OFF_SBOX);
    unsigned char* svalid = (unsigned char*)(smem + OFF_SVAL);
    float4* colbox= (float4*)(smem + OFF_COLBOX);
    float4* large = (float4*)(smem + OFF_LARGE);
    unsigned short* kpos = (unsigned short*)(smem + OFF_KPOS);
    unsigned char*  keepf= (unsigned char*) (smem + OFF_KEEPF);

    __shared__ int wsum[32];
    __shared__ ull ovLoS[128];
    __shared__ ull ovHiS[128];
    __shared__ unsigned char statS[128];
    __shared__ int keptCount;
    __shared__ int colcnt[NCOL];
    __shared__ int lcnt;

    const int b = blockIdx.x, tid = threadIdx.x;
    const int lane = tid & 31, warp = tid >> 5;
    const size_t bT = (size_t)b * TOPK;
    const size_t boff = (size_t)b * NPRIOR;

    for (int i = tid; i < TOPK; i += 1024) {
        sbox[i] = g_boxes[bT + i];
        svalid[i] = ((unsigned)(g_top[bT + i] >> 32)) > KEYTH;
        keepf[i] = 0;
    }
    for (int i = TOPK + tid; i < SPAD; i += 1024) {
        sbox[i] = make_float4(0.f, 0.f, 0.f, 0.f);
        svalid[i] = 0;
    }
    if (tid == 0) { keptCount = 0; lcnt = 0; }
    if (tid < NCOL) colcnt[tid] = 0;
    __syncthreads();

    for (int base = 0; base < TOPK; base += 128) {
#pragma unroll
        for (int q = 0; q < 4; q++) {
            const int ci = q * 32 + warp;
            const int p = base + ci;
            float4 bj = sbox[p];
            float aj = (bj.y - bj.x) * (bj.w - bj.z);
            unsigned m0 = 0, m1 = 0, m2 = 0, m3 = 0;
            for (int q2 = 0; q2 <= q; q2++) {
                bool ob;
                if (q2 < q) ob = pair_sup(sbox[base + q2 * 32 + lane], bj, aj);
                else        ob = (lane < warp) ? pair_sup(sbox[base + q * 32 + lane], bj, aj) : false;
                unsigned bal = __ballot_sync(0xffffffffu, ob);
                if (q2 == 0) m0 = bal; else if (q2 == 1) m1 = bal;
                else if (q2 == 2) m2 = bal; else m3 = bal;
            }
            bool sup = false;
            int c0 = colclamp(bj.x), c1 = colclamp(bj.y);
            for (int c = c0; c <= c1; c++) {
                int n = colcnt[c];
                const float4* cp = colbox + c * COLCAP;
                for (int m = lane; m < n; m += 32)
                    sup |= pair_sup(cp[m], bj, aj);
            }
            {
                int n = lcnt;
                for (int m = lane; m < n; m += 32)
                    sup |= pair_sup(large[m], bj, aj);
            }
            sup = __any_sync(0xffffffffu, sup);
            if (lane == 0) {
                ovLoS[ci] = (ull)m0 | ((ull)m1 << 32);
                ovHiS[ci] = (ull)m2 | ((ull)m3 << 32);
                statS[ci] = (svalid[p] && !sup) ? 1 : 0;
            }
        }
        __syncthreads();

        if (warp == 0) {
            unsigned s0 = __ballot_sync(0xffffffffu, statS[lane]);
            unsigned s1 = __ballot_sync(0xffffffffu, statS[32 + lane]);
            unsigned s2 = __ballot_sync(0xffffffffu, statS[64 + lane]);
            unsigned s3 = __ballot_sync(0xffffffffu, statS[96 + lane]);
            ull aliveLo = (ull)s0 | ((ull)s1 << 32);
            ull aliveHi = (ull)s2 | ((ull)s3 << 32);
            bool cf0, cf1, cf2, cf3;
            {
                int i0 = lane, i1 = 32 + lane, i2 = 64 + lane, i3 = 96 + lane;
                cf0 = ((aliveLo >> i0) & 1ull) && ((ovLoS[i0] & aliveLo) | (ovHiS[i0] & aliveHi));
                cf1 = ((aliveLo >> i1) & 1ull) && ((ovLoS[i1] & aliveLo) | (ovHiS[i1] & aliveHi));
                cf2 = ((aliveHi >> (i2 - 64)) & 1ull) && ((ovLoS[i2] & aliveLo) | (ovHiS[i2] & aliveHi));
                cf3 = ((aliveHi >> (i3 - 64)) & 1ull) && ((ovLoS[i3] & aliveLo) | (ovHiS[i3] & aliveHi));
            }
            unsigned c0b = __ballot_sync(0xffffffffu, cf0);
            unsigned c1b = __ballot_sync(0xffffffffu, cf1);
            unsigned c2b = __ballot_sync(0xffffffffu, cf2);
            unsigned c3b = __ballot_sync(0xffffffffu, cf3);
            ull confLo = (ull)c0b | ((ull)c1b << 32);
            ull confHi = (ull)c2b | ((ull)c3b << 32);
            ull keepLo = aliveLo & ~confLo;
            ull keepHi = aliveHi & ~confHi;
            ull pLo = confLo, pHi = confHi;
            while (pLo | pHi) {
                int i;
                if (pLo) { i = __ffsll((long long)pLo) - 1; pLo &= pLo - 1; }
                else     { i = 64 + __ffsll((long long)pHi) - 1; pHi &= pHi - 1; }
                if (((ovLoS[i] & keepLo) | (ovHiS[i] & keepHi)) == 0ull) {
                    if (i < 64) keepLo |= 1ull << i; else keepHi |= 1ull << (i - 64);
                }
            }
            int b0 = keptCount;
            int totalKeep = __popcll(keepLo) + __popcll(keepHi);
            int nLo = __popcll(keepLo);
#pragma unroll
            for (int k = 0; k < 4; k++) {
                int ci = k * 32 + lane;
                int p = base + ci;
                bool kk = (ci < 64) ? ((keepLo >> ci) & 1ull) : ((keepHi >> (ci - 64)) & 1ull);
                if (p < TOPK) keepf[p] = kk ? 1 : 0;
                if (kk) {
                    int off = (ci < 64) ? __popcll(keepLo & ((1ull << ci) - 1ull))
                                        : nLo + __popcll(keepHi & ((1ull << (ci - 64)) - 1ull));
                    kpos[b0 + off] = (unsigned short)p;
                    float4 bl = sbox[p];
                    int cc0 = colclamp(bl.x), cc1 = colclamp(bl.y);
                    if (cc1 - cc0 >= 3) {
                        int d = atomicAdd(&lcnt, 1);
                        if (d < LARGECAP) large[d] = bl;
                    } else {
                        for (int c = cc0; c <= cc1; c++) {
                            int d = atomicAdd(&colcnt[c], 1);
                            if (d < COLCAP) colbox[c * COLCAP + d] = bl;
                            else { int e = atomicAdd(&lcnt, 1); if (e < LARGECAP) large[e] = bl; }
                        }
                    }
                }
            }
            if (lane == 0) keptCount = b0 + totalKeep;
        }
        __syncthreads();
        if (keptCount >= KEEPK) break;
    }
    __syncthreads();

    int kc = keptCount;
    int kout = kc < KEEPK ? kc : KEEPK;

    // parallel filler: first (KEEPK-kc) non-kept positions, in order
    if (kc < KEEPK) {
        int need = KEEPK - kc;
        int j0 = tid * 5;
        int cnt = 0;
#pragma unroll
        for (int j = 0; j < 5; j++) {
            int p = j0 + j;
            if (p < TOPK && !keepf[p]) cnt++;
        }
        int x = cnt;
#pragma unroll
        for (int o = 1; o < 32; o <<= 1) {
            int n = __shfl_up_sync(0xffffffffu, x, o);
            if (lane >= o) x += n;
        }
        if (lane == 31) wsum[warp] = x;
        __syncthreads();
        if (warp == 0) {
            int w = wsum[lane];
#pragma unroll
            for (int o = 1; o < 32; o <<= 1) {
                int n = __shfl_up_sync(0xffffffffu, w, o);
                if (lane >= o) w += n;
            }
            wsum[lane] = w;
        }
        __syncthreads();
        int pre = (warp ? wsum[warp - 1] : 0) + (x - cnt);
#pragma unroll
        for (int j = 0; j < 5; j++) {
            int p = j0 + j;
            if (p < TOPK && !keepf[p]) {
                if (pre < need) kpos[kc + pre] = (unsigned short)p;
                pre++;
            }
        }
    }
    __syncthreads();

    // write final 750 rows
    for (int r = tid; r < KEEPK; r += 1024) {
        int pos = kpos[r];
        ull key = g_top[bT + pos];
        unsigned idx = ~(unsigned)key;
        unsigned hk = (unsigned)(key >> 32);
        float score = __uint_as_float((hk & 0x80000000u) ? (hk ^ 0x80000000u) : ~hk);
        float px, py, ps; prior_of(idx, px, py, ps);
        const float* bb = bbox + (boff + idx) * 4;
        float cx = px + bb[0] * ps, cy = py + bb[1] * ps;
        float w = ps * expf(bb[2]), h = ps * expf(bb[3]);
        float x1 = cx - w * 0.5f, y1 = cy - h * 0.5f;
        size_t t = (size_t)b * KEEPK + r;
        float* o = out + t * 15;
        o[0] = x1; o[1] = y1; o[2] = x1 + w; o[3] = y1 + h;
        const float* kp = kps + (boff + idx) * 10;
#pragma unroll
        for (int m = 0; m < 5; m++) {
            o[4 + 2 * m] = px + kp[2 * m] * ps;
            o[5 + 2 * m] = py + kp[2 * m + 1] * ps;
        }
        o[14] = score;
        if (write_valid)
            out[(size_t)BATCH * KEEPK * 15 + t] = (r < kout) ? 1.0f : 0.0f;
    }
}

// ---------------- launch ----------------
extern "C" void kernel_launch(void* const* d_in, const int* in_sizes, int n_in,
                              void* d_out, int out_size) {
    const float* cls  = (const float*)d_in[0];
    const float* obj  = (const float*)d_in[1];
    const float* bbox = (const float*)d_in[2];
    const float* kps  = (const float*)d_in[3];
    float* out = (float*)d_out;

    static int attr_set = 0;
    if (!attr_set) {
        cudaFuncSetAttribute(k5_nms, cudaFuncAttributeMaxDynamicSharedMemorySize, SMEM_K5);
        attr_set = 1;
    }

    k1_hist<<<(BATCH * NPRIOR / 4 + 255) / 256, 256>>>(cls, obj);
    k2_scan<<<BATCH, 1024>>>();
    k3_compact<<<(BATCH * NPRIOR / 4 + 255) / 256, 256>>>(cls, obj);
    k4_rank<<<(BATCH * CANDS + 511) / 512, 512>>>(bbox);

    int write_valid = (out_size >= BATCH * KEEPK * 16) ? 1 : 0;
    k5_nms<<<BATCH, 1024, SMEM_K5>>>(bbox, kps, out, write_valid);
}